// round 2
// baseline (speedup 1.0000x reference)
#include <cuda_runtime.h>
#include <cuda_bf16.h>
#include <cooperative_groups.h>
#include <cstdint>

namespace cg = cooperative_groups;

// ---------------------------------------------------------------------------
// Problem constants
// ---------------------------------------------------------------------------
#define BB 16
#define SS 128
#define VV 32000
#define DD 256
#define HH 256
#define TOK (BB * SS)            // 2048 tokens
#define G4H (4 * HH)             // 1024 gate rows
#define KFC (2 * HH)             // 512 = concat(hf, hb)

// ---------------------------------------------------------------------------
// Scratch (device globals; no allocations allowed)
// ---------------------------------------------------------------------------
__device__ float g_emb[TOK * DD];        // [2048, 256]
__device__ float g_xpf[TOK * G4H];       // [2048, 1024]
__device__ float g_xpb[TOK * G4H];       // [2048, 1024]
__device__ float g_afc[TOK * KFC];       // [2048, 512]  (hf | hb)

// ---------------------------------------------------------------------------
// Helpers
// ---------------------------------------------------------------------------
__device__ __forceinline__ float sigf(float x) {
    return 1.0f / (1.0f + expf(-x));
}

__device__ __forceinline__ uint32_t f2tf32(float f) {
    uint32_t r;
    asm volatile("cvt.rna.tf32.f32 %0, %1;\n" : "=r"(r) : "f"(f));
    return r;
}

__device__ __forceinline__ void cp16(void* s, const void* gm) {
    uint32_t sa = (uint32_t)__cvta_generic_to_shared(s);
    asm volatile("cp.async.ca.shared.global [%0], [%1], 16;\n" :: "r"(sa), "l"(gm));
}

__device__ __forceinline__ void mma8(float* c, const uint32_t* a, uint32_t b0, uint32_t b1) {
    asm volatile(
        "mma.sync.aligned.m16n8k8.row.col.f32.tf32.tf32.f32 "
        "{%0,%1,%2,%3}, {%4,%5,%6,%7}, {%8,%9}, {%0,%1,%2,%3};\n"
        : "+f"(c[0]), "+f"(c[1]), "+f"(c[2]), "+f"(c[3])
        : "r"(a[0]), "r"(a[1]), "r"(a[2]), "r"(a[3]), "r"(b0), "r"(b1));
}

// ---------------------------------------------------------------------------
// Kernel 1: embedding gather.  grid=2048, block=64 (one float4 per thread)
// x is int32 (JAX without x64 downcasts jnp.int64 -> int32; harness dtype
// table only carries int32). Clamp defensively so a dtype surprise can't
// turn into an illegal access.
// ---------------------------------------------------------------------------
__global__ void gather_kernel(const int* __restrict__ x,
                              const float* __restrict__ embed,
                              float* __restrict__ emb) {
    int t = blockIdx.x;
    int idx = x[t];
    idx = (idx < 0) ? 0 : ((idx >= VV) ? (VV - 1) : idx);
    const float4* src = (const float4*)(embed + (size_t)idx * DD);
    ((float4*)(emb + (size_t)t * DD))[threadIdx.x] = src[threadIdx.x];
}

// ---------------------------------------------------------------------------
// Kernel 2: generic tf32 GEMM, C[M,N] = A[M,K] @ B[N,K]^T + bias1 (+bias2)
// Tiles: BM=128, BN=128, BK=16, 256 threads (8 warps: 2m x 4n, warp tile 64x32)
// Requires M%128==0, N%128==0, K%16==0 (true for all three uses).
// ---------------------------------------------------------------------------
__global__ __launch_bounds__(256, 2)
void gemm_tf32_kernel(const float* __restrict__ A, const float* __restrict__ B,
                      const float* __restrict__ bias1, const float* __restrict__ bias2,
                      float* __restrict__ C, int M, int N, int K) {
    __shared__ __align__(16) float As[2][128][20];
    __shared__ __align__(16) float Bs[2][128][20];

    const int tid  = threadIdx.x;
    const int bm   = blockIdx.y * 128;
    const int bn   = blockIdx.x * 128;
    const int wid  = tid >> 5, lane = tid & 31;
    const int wm   = wid >> 2, wn = wid & 3;      // 2 x 4 warp grid
    const int g    = lane >> 2, t4 = lane & 3;

    // load mapping: 2 threads per row, 8 cols (32B) each -> two 16B cp.async
    const int lr = tid >> 1;
    const int lh = (tid & 1) * 8;
    const float* Aload = A + (size_t)(bm + lr) * K + lh;
    const float* Bload = B + (size_t)(bn + lr) * K + lh;

    auto load_stage = [&](int buf, int k0) {
        cp16(&As[buf][lr][lh],     Aload + k0);
        cp16(&As[buf][lr][lh + 4], Aload + k0 + 4);
        cp16(&Bs[buf][lr][lh],     Bload + k0);
        cp16(&Bs[buf][lr][lh + 4], Bload + k0 + 4);
        asm volatile("cp.async.commit_group;\n" ::: "memory");
    };

    const int KT = K >> 4;
    load_stage(0, 0);
    if (KT > 1) load_stage(1, 16);

    float acc[4][4][4];
#pragma unroll
    for (int i = 0; i < 4; i++)
#pragma unroll
        for (int j = 0; j < 4; j++)
#pragma unroll
            for (int q = 0; q < 4; q++) acc[i][j][q] = 0.0f;

    for (int kt = 0; kt < KT; kt++) {
        if (kt + 1 < KT) { asm volatile("cp.async.wait_group 1;\n" ::: "memory"); }
        else             { asm volatile("cp.async.wait_group 0;\n" ::: "memory"); }
        __syncthreads();

        const int p = kt & 1;
#pragma unroll
        for (int kk = 0; kk < 16; kk += 8) {
            uint32_t af[4][4];
#pragma unroll
            for (int im = 0; im < 4; im++) {
                const float* ap = &As[p][wm * 64 + im * 16 + g][kk + t4];
                af[im][0] = f2tf32(ap[0]);
                af[im][1] = f2tf32(ap[8 * 20]);
                af[im][2] = f2tf32(ap[4]);
                af[im][3] = f2tf32(ap[8 * 20 + 4]);
            }
#pragma unroll
            for (int in = 0; in < 4; in++) {
                const float* bp = &Bs[p][wn * 32 + in * 8 + g][kk + t4];
                uint32_t b0 = f2tf32(bp[0]);
                uint32_t b1 = f2tf32(bp[4]);
#pragma unroll
                for (int im = 0; im < 4; im++) mma8(acc[im][in], af[im], b0, b1);
            }
        }
        __syncthreads();
        if (kt + 2 < KT) load_stage(kt & 1, (kt + 2) << 4);
    }

    // epilogue
#pragma unroll
    for (int im = 0; im < 4; im++) {
        int row0 = bm + wm * 64 + im * 16 + g;
#pragma unroll
        for (int in = 0; in < 4; in++) {
            int col0 = bn + wn * 32 + in * 8 + t4 * 2;
            float bb0 = bias1[col0]     + (bias2 ? bias2[col0]     : 0.0f);
            float bb1 = bias1[col0 + 1] + (bias2 ? bias2[col0 + 1] : 0.0f);
            float2 v0 = make_float2(acc[im][in][0] + bb0, acc[im][in][1] + bb1);
            float2 v1 = make_float2(acc[im][in][2] + bb0, acc[im][in][3] + bb1);
            *(float2*)&C[(size_t)row0 * N + col0]       = v0;
            *(float2*)&C[(size_t)(row0 + 8) * N + col0] = v1;
        }
    }
}

// ---------------------------------------------------------------------------
// Kernel 3: backward direction = single LSTM cell step from zero state.
// hb = sigmoid(o) * tanh(sigmoid(i) * tanh(g)).  grid=2048, block=256
// ---------------------------------------------------------------------------
__global__ void hb_kernel(const float* __restrict__ xpb, float* __restrict__ afc) {
    int t = blockIdx.x;
    int j = threadIdx.x;
    const float* gp = xpb + (size_t)t * G4H;
    float gi = sigf(gp[j]);
    float gg = tanhf(gp[2 * HH + j]);
    float go = sigf(gp[3 * HH + j]);
    float cb = gi * gg;
    afc[(size_t)t * KFC + HH + j] = go * tanhf(cb);
}

// ---------------------------------------------------------------------------
// Kernel 4: forward LSTM scan.
// One 8-CTA cluster per batch (16 clusters = 128 CTAs), 512 threads/CTA.
// Each CTA owns 32 h-indices (128 gate rows); W_hh slice (128KB) lives in
// registers (64 floats/thread). h broadcast via DSMEM pull + cluster.sync.
// ---------------------------------------------------------------------------
__global__ __launch_bounds__(512, 1) __cluster_dims__(8, 1, 1)
void lstm_scan_kernel(const float* __restrict__ xpf,
                      const float* __restrict__ w_hh,
                      float* __restrict__ afc) {
    cg::cluster_group cluster = cg::this_cluster();
    const int rank  = cluster.block_rank();            // 0..7
    const int batch = blockIdx.x >> 3;                 // 0..15
    const int tid   = threadIdx.x;
    const int r     = tid & 127;                       // local gate row 0..127
    const int kc    = tid >> 7;                        // k-quarter 0..3
    const int hbase = rank * 32;
    const int sub   = r >> 5, rr = r & 31;
    const int grow  = sub * HH + hbase + rr;           // global gate row 0..1023

    __shared__ __align__(16) float h_full[2][HH];
    __shared__ float part[4][128];
    __shared__ float pre[128];

    // W_hh slice into registers: 16 float4 = 64 values
    float4 wv[16];
    {
        const float4* wrow = (const float4*)(w_hh + (size_t)grow * HH + kc * 64);
#pragma unroll
        for (int j = 0; j < 16; j++) wv[j] = wrow[j];
    }

    if (tid < HH) h_full[0][tid] = 0.0f;
    float creg = 0.0f;
    __syncthreads();

    const float* xp  = xpf + (size_t)(batch * SS) * G4H;
    float*       out = afc + (size_t)(batch * SS) * KFC;

    int cur = 0;
    for (int s = 0; s < SS; s++) {
        // partial dot products: thread (r, kc) covers k in [kc*64, kc*64+64)
        float4 a4 = make_float4(0.f, 0.f, 0.f, 0.f);
        const float4* hv = (const float4*)(h_full[cur] + kc * 64);
#pragma unroll
        for (int j = 0; j < 16; j++) {
            float4 h4 = hv[j];
            a4.x += wv[j].x * h4.x;
            a4.y += wv[j].y * h4.y;
            a4.z += wv[j].z * h4.z;
            a4.w += wv[j].w * h4.w;
        }
        part[kc][r] = (a4.x + a4.y) + (a4.z + a4.w);
        __syncthreads();

        if (tid < 128) {
            // r == tid here (kc == 0)
            pre[tid] = part[0][tid] + part[1][tid] + part[2][tid] + part[3][tid]
                     + xp[(size_t)s * G4H + grow];
        }
        __syncthreads();

        const int nxt = cur ^ 1;
        if (tid < 32) {
            float gi = sigf(pre[tid]);
            float gf = sigf(pre[32 + tid]);
            float gg = tanhf(pre[64 + tid]);
            float go = sigf(pre[96 + tid]);
            creg = gf * creg + gi * gg;
            float hval = go * tanhf(creg);
            h_full[nxt][hbase + tid] = hval;
            out[(size_t)s * KFC + hbase + tid] = hval;
        }

        cluster.sync();

        // pull the 7 peer slices into the local copy of h
        if (tid < HH) {
            int owner = tid >> 5;
            if (owner != rank) {
                const float* src =
                    (const float*)cluster.map_shared_rank((void*)&h_full[nxt][tid], owner);
                h_full[nxt][tid] = *src;
            }
        }
        __syncthreads();
        cur = nxt;
    }
}

// ---------------------------------------------------------------------------
// kernel_launch
// ---------------------------------------------------------------------------
extern "C" void kernel_launch(void* const* d_in, const int* in_sizes, int n_in,
                              void* d_out, int out_size) {
    const int* x            = (const int*)d_in[0];
    const float* embed      = (const float*)d_in[1];
    const float* w_ih_f     = (const float*)d_in[2];
    const float* w_hh_f     = (const float*)d_in[3];
    const float* b_ih_f     = (const float*)d_in[4];
    const float* b_hh_f     = (const float*)d_in[5];
    const float* w_ih_b     = (const float*)d_in[6];
    const float* w_hh_b     = (const float*)d_in[7];  (void)w_hh_b;
    const float* b_ih_b     = (const float*)d_in[8];
    const float* b_hh_b     = (const float*)d_in[9];
    const float* fc_w       = (const float*)d_in[10];
    const float* fc_b       = (const float*)d_in[11];
    float* out              = (float*)d_out;
    (void)in_sizes; (void)n_in; (void)out_size;

    float *emb, *xpf, *xpb, *afc;
    cudaGetSymbolAddress((void**)&emb, g_emb);
    cudaGetSymbolAddress((void**)&xpf, g_xpf);
    cudaGetSymbolAddress((void**)&xpb, g_xpb);
    cudaGetSymbolAddress((void**)&afc, g_afc);

    // 1) embedding gather
    gather_kernel<<<TOK, 64>>>(x, embed, emb);

    // 2) input projections (tf32 GEMM):  xp = emb @ w_ih^T + b_ih + b_hh
    gemm_tf32_kernel<<<dim3(G4H / 128, TOK / 128), 256>>>(
        emb, w_ih_f, b_ih_f, b_hh_f, xpf, TOK, G4H, DD);
    gemm_tf32_kernel<<<dim3(G4H / 128, TOK / 128), 256>>>(
        emb, w_ih_b, b_ih_b, b_hh_b, xpb, TOK, G4H, DD);

    // 3) backward direction (elementwise) -> afc[:, 256:512]
    hb_kernel<<<TOK, 256>>>(xpb, afc);

    // 4) forward LSTM scan -> afc[:, 0:256]
    lstm_scan_kernel<<<BB * 8, 512>>>(xpf, w_hh_f, afc);

    // 5) logits = afc @ fc_w^T + fc_b
    gemm_tf32_kernel<<<dim3(VV / 128, TOK / 128), 256>>>(
        afc, fc_w, fc_b, nullptr, out, TOK, VV, KFC);
}

// round 7
// speedup vs baseline: 1.0003x; 1.0003x over previous
#include <cuda_runtime.h>
#include <cuda_bf16.h>
#include <cooperative_groups.h>
#include <cstdint>

namespace cg = cooperative_groups;

// ---------------------------------------------------------------------------
// Problem constants
// ---------------------------------------------------------------------------
#define BB 16
#define SS 128
#define VV 32000
#define DD 256
#define HH 256
#define TOK (BB * SS)            // 2048 tokens
#define G4H (4 * HH)             // 1024 gate rows
#define KFC (2 * HH)             // 512 = concat(hf, hb)

// ---------------------------------------------------------------------------
// Scratch (device globals; no allocations allowed)
// ---------------------------------------------------------------------------
__device__ float g_emb[TOK * DD];        // [2048, 256]
__device__ float g_xpf[TOK * G4H];       // [2048, 1024]
__device__ float g_xpb[TOK * G4H];       // [2048, 1024]
__device__ float g_afc[TOK * KFC];       // [2048, 512]  (hf | hb), tf32-rounded
__device__ float g_fcw[VV * KFC];        // [32000, 512] fc_w pre-rounded to tf32

// ---------------------------------------------------------------------------
// Helpers
// ---------------------------------------------------------------------------
__device__ __forceinline__ float sigf(float x) {
    return 1.0f / (1.0f + expf(-x));
}

__device__ __forceinline__ uint32_t f2tf32(float f) {
    uint32_t r;
    asm volatile("cvt.rna.tf32.f32 %0, %1;\n" : "=r"(r) : "f"(f));
    return r;
}

__device__ __forceinline__ float tf32r(float f) {
    return __uint_as_float(f2tf32(f));
}

__device__ __forceinline__ uint32_t smem_u32(const void* p) {
    return (uint32_t)__cvta_generic_to_shared(p);
}

__device__ __forceinline__ void cp16(void* s, const void* gm) {
    uint32_t sa = smem_u32(s);
    asm volatile("cp.async.ca.shared.global [%0], [%1], 16;\n" :: "r"(sa), "l"(gm));
}

__device__ __forceinline__ void cp_commit() {
    asm volatile("cp.async.commit_group;\n" ::: "memory");
}

__device__ __forceinline__ void mma8(float* c, const uint32_t* a, uint32_t b0, uint32_t b1) {
    asm volatile(
        "mma.sync.aligned.m16n8k8.row.col.f32.tf32.tf32.f32 "
        "{%0,%1,%2,%3}, {%4,%5,%6,%7}, {%8,%9}, {%0,%1,%2,%3};\n"
        : "+f"(c[0]), "+f"(c[1]), "+f"(c[2]), "+f"(c[3])
        : "r"(a[0]), "r"(a[1]), "r"(a[2]), "r"(a[3]), "r"(b0), "r"(b1));
}

// ---------------------------------------------------------------------------
// Kernel 0: pre-round fc_w to tf32 (rna) into g_fcw.  16.4M elems, float4.
// ---------------------------------------------------------------------------
__global__ void cvt_fcw_kernel(const float* __restrict__ src, float* __restrict__ dst) {
    int i = (blockIdx.x * 256 + threadIdx.x) * 4;
    float4 v = *(const float4*)(src + i);
    v.x = tf32r(v.x); v.y = tf32r(v.y); v.z = tf32r(v.z); v.w = tf32r(v.w);
    *(float4*)(dst + i) = v;
}

// ---------------------------------------------------------------------------
// Kernel 1: embedding gather.  x is int32.
// ---------------------------------------------------------------------------
__global__ void gather_kernel(const int* __restrict__ x,
                              const float* __restrict__ embed,
                              float* __restrict__ emb) {
    int t = blockIdx.x;
    int idx = x[t];
    idx = (idx < 0) ? 0 : ((idx >= VV) ? (VV - 1) : idx);
    const float4* src = (const float4*)(embed + (size_t)idx * DD);
    ((float4*)(emb + (size_t)t * DD))[threadIdx.x] = src[threadIdx.x];
}

// ---------------------------------------------------------------------------
// Kernel 2: mma.sync tf32 GEMM, C[M,N] = A[M,K] @ B[N,K]^T + bias1 (+bias2)
// Tiles: BM=128, BN=128, BK=16, 256 threads (8 warps: 2m x 4n, warp tile 64x32)
// DO_CVT=false assumes A and B are pre-rounded to tf32 (skips cvt in the
// inner loop — ~30% of issue slots).
// ---------------------------------------------------------------------------
template <bool DO_CVT>
__global__ __launch_bounds__(256, 2)
void gemm_tf32_kernel(const float* __restrict__ A, const float* __restrict__ B,
                      const float* __restrict__ bias1, const float* __restrict__ bias2,
                      float* __restrict__ C, int M, int N, int K) {
    __shared__ __align__(16) float As[2][128][20];
    __shared__ __align__(16) float Bs[2][128][20];

    const int tid  = threadIdx.x;
    const int bm   = blockIdx.y * 128;
    const int bn   = blockIdx.x * 128;
    const int wid  = tid >> 5, lane = tid & 31;
    const int wm   = wid >> 2, wn = wid & 3;      // 2 x 4 warp grid
    const int g    = lane >> 2, t4 = lane & 3;

    const int lr = tid >> 1;
    const int lh = (tid & 1) * 8;
    const float* Aload = A + (size_t)(bm + lr) * K + lh;
    const float* Bload = B + (size_t)(bn + lr) * K + lh;

    auto load_stage = [&](int buf, int k0) {
        cp16(&As[buf][lr][lh],     Aload + k0);
        cp16(&As[buf][lr][lh + 4], Aload + k0 + 4);
        cp16(&Bs[buf][lr][lh],     Bload + k0);
        cp16(&Bs[buf][lr][lh + 4], Bload + k0 + 4);
        cp_commit();
    };

    const int KT = K >> 4;
    load_stage(0, 0);
    if (KT > 1) load_stage(1, 16);

    float acc[4][4][4];
#pragma unroll
    for (int i = 0; i < 4; i++)
#pragma unroll
        for (int j = 0; j < 4; j++)
#pragma unroll
            for (int q = 0; q < 4; q++) acc[i][j][q] = 0.0f;

    auto rd = [&](const float* p) -> uint32_t {
        if (DO_CVT) return f2tf32(*p);
        return __float_as_uint(*p);
    };

    for (int kt = 0; kt < KT; kt++) {
        if (kt + 1 < KT) { asm volatile("cp.async.wait_group 1;\n" ::: "memory"); }
        else             { asm volatile("cp.async.wait_group 0;\n" ::: "memory"); }
        __syncthreads();

        const int p = kt & 1;
#pragma unroll
        for (int kk = 0; kk < 16; kk += 8) {
            uint32_t af[4][4];
#pragma unroll
            for (int im = 0; im < 4; im++) {
                const float* ap = &As[p][wm * 64 + im * 16 + g][kk + t4];
                af[im][0] = rd(ap);
                af[im][1] = rd(ap + 8 * 20);
                af[im][2] = rd(ap + 4);
                af[im][3] = rd(ap + 8 * 20 + 4);
            }
#pragma unroll
            for (int in = 0; in < 4; in++) {
                const float* bp = &Bs[p][wn * 32 + in * 8 + g][kk + t4];
                uint32_t b0 = rd(bp);
                uint32_t b1 = rd(bp + 4);
#pragma unroll
                for (int im = 0; im < 4; im++) mma8(acc[im][in], af[im], b0, b1);
            }
        }
        __syncthreads();
        if (kt + 2 < KT) load_stage(kt & 1, (kt + 2) << 4);
    }

#pragma unroll
    for (int im = 0; im < 4; im++) {
        int row0 = bm + wm * 64 + im * 16 + g;
#pragma unroll
        for (int in = 0; in < 4; in++) {
            int col0 = bn + wn * 32 + in * 8 + t4 * 2;
            float bb0 = bias1[col0]     + (bias2 ? bias2[col0]     : 0.0f);
            float bb1 = bias1[col0 + 1] + (bias2 ? bias2[col0 + 1] : 0.0f);
            float2 v0 = make_float2(acc[im][in][0] + bb0, acc[im][in][1] + bb1);
            float2 v1 = make_float2(acc[im][in][2] + bb0, acc[im][in][3] + bb1);
            *(float2*)&C[(size_t)row0 * N + col0]       = v0;
            *(float2*)&C[(size_t)(row0 + 8) * N + col0] = v1;
        }
    }
}

// ---------------------------------------------------------------------------
// Kernel 3: backward direction = single LSTM cell step from zero state.
// Writes tf32-rounded hb so the fc GEMM can skip cvt.
// ---------------------------------------------------------------------------
__global__ void hb_kernel(const float* __restrict__ xpb, float* __restrict__ afc) {
    int t = blockIdx.x;
    int j = threadIdx.x;
    const float* gp = xpb + (size_t)t * G4H;
    float gi = sigf(gp[j]);
    float gg = tanhf(gp[2 * HH + j]);
    float go = sigf(gp[3 * HH + j]);
    float cb = gi * gg;
    afc[(size_t)t * KFC + HH + j] = tf32r(go * tanhf(cb));
}

// ---------------------------------------------------------------------------
// Kernel 4: forward LSTM scan (8-CTA cluster per batch).
// h kept in full fp32 for the recurrence; only the afc output copy is
// tf32-rounded (for the fc GEMM).
// ---------------------------------------------------------------------------
__global__ __launch_bounds__(512, 1) __cluster_dims__(8, 1, 1)
void lstm_scan_kernel(const float* __restrict__ xpf,
                      const float* __restrict__ w_hh,
                      float* __restrict__ afc) {
    cg::cluster_group cluster = cg::this_cluster();
    const int rank  = cluster.block_rank();
    const int batch = blockIdx.x >> 3;
    const int tid   = threadIdx.x;
    const int r     = tid & 127;
    const int kc    = tid >> 7;
    const int hbase = rank * 32;
    const int sub   = r >> 5, rr = r & 31;
    const int grow  = sub * HH + hbase + rr;

    __shared__ __align__(16) float h_full[2][HH];
    __shared__ float part[4][128];
    __shared__ float pre[128];

    float4 wv[16];
    {
        const float4* wrow = (const float4*)(w_hh + (size_t)grow * HH + kc * 64);
#pragma unroll
        for (int j = 0; j < 16; j++) wv[j] = wrow[j];
    }

    if (tid < HH) h_full[0][tid] = 0.0f;
    float creg = 0.0f;
    __syncthreads();

    const float* xp  = xpf + (size_t)(batch * SS) * G4H;
    float*       out = afc + (size_t)(batch * SS) * KFC;

    int cur = 0;
    for (int s = 0; s < SS; s++) {
        float4 a4 = make_float4(0.f, 0.f, 0.f, 0.f);
        const float4* hv = (const float4*)(h_full[cur] + kc * 64);
#pragma unroll
        for (int j = 0; j < 16; j++) {
            float4 h4 = hv[j];
            a4.x += wv[j].x * h4.x;
            a4.y += wv[j].y * h4.y;
            a4.z += wv[j].z * h4.z;
            a4.w += wv[j].w * h4.w;
        }
        part[kc][r] = (a4.x + a4.y) + (a4.z + a4.w);
        __syncthreads();

        if (tid < 128) {
            pre[tid] = part[0][tid] + part[1][tid] + part[2][tid] + part[3][tid]
                     + xp[(size_t)s * G4H + grow];
        }
        __syncthreads();

        const int nxt = cur ^ 1;
        if (tid < 32) {
            float gi = sigf(pre[tid]);
            float gf = sigf(pre[32 + tid]);
            float gg = tanhf(pre[64 + tid]);
            float go = sigf(pre[96 + tid]);
            creg = gf * creg + gi * gg;
            float hval = go * tanhf(creg);
            h_full[nxt][hbase + tid] = hval;
            out[(size_t)s * KFC + hbase + tid] = tf32r(hval);
        }

        cluster.sync();

        if (tid < HH) {
            int owner = tid >> 5;
            if (owner != rank) {
                const float* src =
                    (const float*)cluster.map_shared_rank((void*)&h_full[nxt][tid], owner);
                h_full[nxt][tid] = *src;
            }
        }
        __syncthreads();
        cur = nxt;
    }
}

// ---------------------------------------------------------------------------
// kernel_launch
// ---------------------------------------------------------------------------
extern "C" void kernel_launch(void* const* d_in, const int* in_sizes, int n_in,
                              void* d_out, int out_size) {
    const int* x            = (const int*)d_in[0];
    const float* embed      = (const float*)d_in[1];
    const float* w_ih_f     = (const float*)d_in[2];
    const float* w_hh_f     = (const float*)d_in[3];
    const float* b_ih_f     = (const float*)d_in[4];
    const float* b_hh_f     = (const float*)d_in[5];
    const float* w_ih_b     = (const float*)d_in[6];
    const float* w_hh_b     = (const float*)d_in[7];  (void)w_hh_b;
    const float* b_ih_b     = (const float*)d_in[8];
    const float* b_hh_b     = (const float*)d_in[9];
    const float* fc_w       = (const float*)d_in[10];
    const float* fc_b       = (const float*)d_in[11];
    float* out              = (float*)d_out;
    (void)in_sizes; (void)n_in; (void)out_size;

    float *emb, *xpf, *xpb, *afc, *fcw;
    cudaGetSymbolAddress((void**)&emb, g_emb);
    cudaGetSymbolAddress((void**)&xpf, g_xpf);
    cudaGetSymbolAddress((void**)&xpb, g_xpb);
    cudaGetSymbolAddress((void**)&afc, g_afc);
    cudaGetSymbolAddress((void**)&fcw, g_fcw);

    // 0) pre-round fc_w to tf32 (independent of the rest; overlaps)
    cvt_fcw_kernel<<<(VV * KFC) / (256 * 4), 256>>>(fc_w, fcw);

    // 1) embedding gather
    gather_kernel<<<TOK, 64>>>(x, embed, emb);

    // 2) input projections (cvt in-loop; inputs unrounded)
    gemm_tf32_kernel<true><<<dim3(G4H / 128, TOK / 128), 256>>>(
        emb, w_ih_f, b_ih_f, b_hh_f, xpf, TOK, G4H, DD);
    gemm_tf32_kernel<true><<<dim3(G4H / 128, TOK / 128), 256>>>(
        emb, w_ih_b, b_ih_b, b_hh_b, xpb, TOK, G4H, DD);

    // 3) backward direction -> afc[:, 256:512] (tf32-rounded)
    hb_kernel<<<TOK, 256>>>(xpb, afc);

    // 4) forward LSTM scan -> afc[:, 0:256] (tf32-rounded)
    lstm_scan_kernel<<<BB * 8, 512>>>(xpf, w_hh_f, afc);

    // 5) logits = afc @ fcw^T + fc_b (no cvt in inner loop)
    gemm_tf32_kernel<false><<<dim3(VV / 128, TOK / 128), 256>>>(
        afc, fcw, fc_b, nullptr, out, TOK, VV, KFC);
}